// round 1
// baseline (speedup 1.0000x reference)
#include <cuda_runtime.h>
#include <cstdint>
#include <cstddef>

// ---------------- Problem constants ----------------
#define NNODES 200000
#define NEDGES 400000
#define NGRAPHS 4096
#define HDIM 300
#define H2DIM 600
#define NLAYERS 5

// ---------------- Scratch (device globals; no allocation allowed) ----------------
__device__ float g_h[(size_t)NNODES * HDIM];     // node features (ping)
__device__ float g_agg[(size_t)NNODES * HDIM];   // scatter-add accumulator
__device__ float g_t[(size_t)NNODES * H2DIM];    // hidden 2H activations
__device__ float g_gsum[(size_t)NGRAPHS * HDIM]; // pooled sums
__device__ float g_gcnt[NGRAPHS];                // pooled counts

// ---------------- PTX helpers ----------------
__device__ __forceinline__ unsigned long long pk2(float x) {
    unsigned long long d;
    asm("mov.b64 %0, {%1, %1};" : "=l"(d) : "f"(x));
    return d;
}
__device__ __forceinline__ void fma2(unsigned long long& d, unsigned long long a, unsigned long long b) {
    asm("fma.rn.f32x2 %0, %1, %2, %0;" : "+l"(d) : "l"(a), "l"(b));
}
__device__ __forceinline__ float2 upk(unsigned long long v) {
    float2 r;
    asm("mov.b64 {%0, %1}, %2;" : "=f"(r.x), "=f"(r.y) : "l"(v));
    return r;
}
__device__ __forceinline__ void red_add_v4(float* p, float4 v) {
    asm volatile("red.global.add.v4.f32 [%0], {%1, %2, %3, %4};"
                 :: "l"(p), "f"(v.x), "f"(v.y), "f"(v.z), "f"(v.w) : "memory");
}

// ---------------- Zeroing kernels (reference device symbols directly) ----------------
__global__ void zero_agg_kernel() {
    float4* p = reinterpret_cast<float4*>(g_agg);
    int n4 = (NNODES * HDIM) / 4;
    for (int i = blockIdx.x * blockDim.x + threadIdx.x; i < n4; i += gridDim.x * blockDim.x)
        p[i] = make_float4(0.f, 0.f, 0.f, 0.f);
}
__global__ void zero_pool_kernel() {
    float4* p = reinterpret_cast<float4*>(g_gsum);
    int n4 = (NGRAPHS * HDIM) / 4;
    for (int i = blockIdx.x * blockDim.x + threadIdx.x; i < n4; i += gridDim.x * blockDim.x)
        p[i] = make_float4(0.f, 0.f, 0.f, 0.f);
    for (int i = blockIdx.x * blockDim.x + threadIdx.x; i < NGRAPHS; i += gridDim.x * blockDim.x)
        g_gcnt[i] = 0.f;
}

// ---------------- Atom encoder: h[n] = sum_f atom_emb[f, x[n,f], :] ----------------
__global__ void atom_kernel(const int* __restrict__ x, const float* __restrict__ atom_emb) {
    int n = blockIdx.x;
    __shared__ int sx[9];
    if (threadIdx.x < 9) sx[threadIdx.x] = x[n * 9 + threadIdx.x];
    __syncthreads();
    for (int j = threadIdx.x; j < HDIM; j += blockDim.x) {
        float s = 0.f;
#pragma unroll
        for (int f = 0; f < 9; f++)
            s += __ldg(&atom_emb[((size_t)(f * 120 + sx[f])) * HDIM + j]);
        g_h[(size_t)n * HDIM + j] = s;
    }
}

// ---------------- Edge kernel: agg[dst] += relu(h[src] + e) ----------------
// warp per edge; H=300 -> 75 float4 chunks
__global__ void edge_kernel(const int* __restrict__ edge_index,
                            const int* __restrict__ edge_attr,
                            const float* __restrict__ bond_l) {
    int e = blockIdx.x * 8 + (threadIdx.x >> 5);
    if (e >= NEDGES) return;
    int lane = threadIdx.x & 31;
    int src = __ldg(&edge_index[e]);
    int dst = __ldg(&edge_index[NEDGES + e]);
    int a0 = __ldg(&edge_attr[e * 3 + 0]);
    int a1 = __ldg(&edge_attr[e * 3 + 1]);
    int a2 = __ldg(&edge_attr[e * 3 + 2]);
    const float4* b0 = reinterpret_cast<const float4*>(bond_l + (size_t)(0 * 16 + a0) * HDIM);
    const float4* b1 = reinterpret_cast<const float4*>(bond_l + (size_t)(1 * 16 + a1) * HDIM);
    const float4* b2 = reinterpret_cast<const float4*>(bond_l + (size_t)(2 * 16 + a2) * HDIM);
    const float4* hs = reinterpret_cast<const float4*>(g_h + (size_t)src * HDIM);
    float* ag = g_agg + (size_t)dst * HDIM;
#pragma unroll 3
    for (int c = lane; c < HDIM / 4; c += 32) {
        float4 e0 = __ldg(&b0[c]);
        float4 e1 = __ldg(&b1[c]);
        float4 e2 = __ldg(&b2[c]);
        float4 hv = hs[c];
        float4 m;
        m.x = fmaxf(hv.x + e0.x + e1.x + e2.x, 0.f);
        m.y = fmaxf(hv.y + e0.y + e1.y + e2.y, 0.f);
        m.z = fmaxf(hv.z + e0.z + e1.z + e2.z, 0.f);
        m.w = fmaxf(hv.w + e0.w + e1.w + e2.w, 0.f);
        red_add_v4(ag + 4 * c, m);
    }
}

// ---------------- GEMM 1 (fused): t = relu(BN((((1+eps)h + agg) @ W1) + b1)) ----------------
// BM=128, BN=64, TK=16, 256 threads, 8x4 micro-tile, f32x2 FMAs.
#define BM 128
#define BN 64
#define TK 16

__global__ __launch_bounds__(256) void gemm1_kernel(
    const float* __restrict__ W1l, const float* __restrict__ b1l,
    const float* __restrict__ gml, const float* __restrict__ btl,
    const float* __restrict__ mnl, const float* __restrict__ vrl,
    const float* __restrict__ epsp) {
    __shared__ float As[TK][BM];
    __shared__ float Bs[TK][BN];
    const int K = HDIM, NC = H2DIM;
    int tid = threadIdx.x;
    int rowBase = blockIdx.y * BM;
    int colBase = blockIdx.x * BN;
    float epv = 1.0f + __ldg(epsp);
    int tx = tid & 15, ty = tid >> 4;

    unsigned long long acc[16];
#pragma unroll
    for (int i = 0; i < 16; i++) acc[i] = 0ull;

    int nkt = (K + TK - 1) / TK;
    for (int kt = 0; kt < nkt; kt++) {
        // A tile: combine (1+eps)*h + agg on the fly
#pragma unroll
        for (int i = 0; i < 2; i++) {
            int c = tid + i * 256;
            int row = c >> 2, kq = c & 3;
            int gk = kt * TK + kq * 4;
            int gr = rowBase + row;
            float4 av = make_float4(0.f, 0.f, 0.f, 0.f);
            if (gk < K && gr < NNODES) {
                float4 hv = *reinterpret_cast<const float4*>(g_h + (size_t)gr * HDIM + gk);
                float4 gv = *reinterpret_cast<const float4*>(g_agg + (size_t)gr * HDIM + gk);
                av.x = fmaf(epv, hv.x, gv.x);
                av.y = fmaf(epv, hv.y, gv.y);
                av.z = fmaf(epv, hv.z, gv.z);
                av.w = fmaf(epv, hv.w, gv.w);
            }
            As[kq * 4 + 0][row] = av.x;
            As[kq * 4 + 1][row] = av.y;
            As[kq * 4 + 2][row] = av.z;
            As[kq * 4 + 3][row] = av.w;
        }
        // B tile
        {
            int n4 = tid & 15, kr = tid >> 4;
            int gk = kt * TK + kr;
            int gc = colBase + n4 * 4;
            float4 bv = make_float4(0.f, 0.f, 0.f, 0.f);
            if (gk < K && gc < NC)
                bv = *reinterpret_cast<const float4*>(W1l + (size_t)gk * NC + gc);
            *reinterpret_cast<float4*>(&Bs[kr][n4 * 4]) = bv;
        }
        __syncthreads();
#pragma unroll
        for (int k = 0; k < TK; k++) {
            ulonglong2 aA = *reinterpret_cast<const ulonglong2*>(&As[k][ty * 8]);
            ulonglong2 aB = *reinterpret_cast<const ulonglong2*>(&As[k][ty * 8 + 4]);
            float4 bv = *reinterpret_cast<const float4*>(&Bs[k][tx * 4]);
            unsigned long long bp0 = pk2(bv.x), bp1 = pk2(bv.y), bp2 = pk2(bv.z), bp3 = pk2(bv.w);
            fma2(acc[0], aA.x, bp0);  fma2(acc[1], aA.y, bp0);  fma2(acc[2], aB.x, bp0);  fma2(acc[3], aB.y, bp0);
            fma2(acc[4], aA.x, bp1);  fma2(acc[5], aA.y, bp1);  fma2(acc[6], aB.x, bp1);  fma2(acc[7], aB.y, bp1);
            fma2(acc[8], aA.x, bp2);  fma2(acc[9], aA.y, bp2);  fma2(acc[10], aB.x, bp2); fma2(acc[11], aB.y, bp2);
            fma2(acc[12], aA.x, bp3); fma2(acc[13], aA.y, bp3); fma2(acc[14], aB.x, bp3); fma2(acc[15], aB.y, bp3);
        }
        __syncthreads();
    }
    // Epilogue: BN (eval) + ReLU
    float o[8][4];
#pragma unroll
    for (int c = 0; c < 4; c++)
#pragma unroll
        for (int rp = 0; rp < 4; rp++) {
            float2 v = upk(acc[c * 4 + rp]);
            o[rp * 2][c] = v.x;
            o[rp * 2 + 1][c] = v.y;
        }
    int gc0 = colBase + tx * 4;
    if (gc0 < NC) {
        float s[4], t[4];
#pragma unroll
        for (int c = 0; c < 4; c++) {
            int col = gc0 + c;
            float sc = __ldg(&gml[col]) * rsqrtf(__ldg(&vrl[col]) + 1e-5f);
            s[c] = sc;
            t[c] = (__ldg(&b1l[col]) - __ldg(&mnl[col])) * sc + __ldg(&btl[col]);
        }
#pragma unroll
        for (int r = 0; r < 8; r++) {
            int gr = rowBase + ty * 8 + r;
            if (gr < NNODES) {
                float4 v;
                v.x = fmaxf(fmaf(o[r][0], s[0], t[0]), 0.f);
                v.y = fmaxf(fmaf(o[r][1], s[1], t[1]), 0.f);
                v.z = fmaxf(fmaf(o[r][2], s[2], t[2]), 0.f);
                v.w = fmaxf(fmaf(o[r][3], s[3], t[3]), 0.f);
                *reinterpret_cast<float4*>(g_t + (size_t)gr * H2DIM + gc0) = v;
            }
        }
    }
}

// ---------------- GEMM 2: h = t @ W2 + b2 ----------------
__global__ __launch_bounds__(256) void gemm2_kernel(const float* __restrict__ W2l,
                                                    const float* __restrict__ b2l) {
    __shared__ float As[TK][BM];
    __shared__ float Bs[TK][BN];
    const int K = H2DIM, NC = HDIM;
    int tid = threadIdx.x;
    int rowBase = blockIdx.y * BM;
    int colBase = blockIdx.x * BN;
    int tx = tid & 15, ty = tid >> 4;

    unsigned long long acc[16];
#pragma unroll
    for (int i = 0; i < 16; i++) acc[i] = 0ull;

    int nkt = (K + TK - 1) / TK;
    for (int kt = 0; kt < nkt; kt++) {
#pragma unroll
        for (int i = 0; i < 2; i++) {
            int c = tid + i * 256;
            int row = c >> 2, kq = c & 3;
            int gk = kt * TK + kq * 4;
            int gr = rowBase + row;
            float4 av = make_float4(0.f, 0.f, 0.f, 0.f);
            if (gk < K && gr < NNODES)
                av = *reinterpret_cast<const float4*>(g_t + (size_t)gr * H2DIM + gk);
            As[kq * 4 + 0][row] = av.x;
            As[kq * 4 + 1][row] = av.y;
            As[kq * 4 + 2][row] = av.z;
            As[kq * 4 + 3][row] = av.w;
        }
        {
            int n4 = tid & 15, kr = tid >> 4;
            int gk = kt * TK + kr;
            int gc = colBase + n4 * 4;
            float4 bv = make_float4(0.f, 0.f, 0.f, 0.f);
            if (gk < K && gc < NC)
                bv = *reinterpret_cast<const float4*>(W2l + (size_t)gk * NC + gc);
            *reinterpret_cast<float4*>(&Bs[kr][n4 * 4]) = bv;
        }
        __syncthreads();
#pragma unroll
        for (int k = 0; k < TK; k++) {
            ulonglong2 aA = *reinterpret_cast<const ulonglong2*>(&As[k][ty * 8]);
            ulonglong2 aB = *reinterpret_cast<const ulonglong2*>(&As[k][ty * 8 + 4]);
            float4 bv = *reinterpret_cast<const float4*>(&Bs[k][tx * 4]);
            unsigned long long bp0 = pk2(bv.x), bp1 = pk2(bv.y), bp2 = pk2(bv.z), bp3 = pk2(bv.w);
            fma2(acc[0], aA.x, bp0);  fma2(acc[1], aA.y, bp0);  fma2(acc[2], aB.x, bp0);  fma2(acc[3], aB.y, bp0);
            fma2(acc[4], aA.x, bp1);  fma2(acc[5], aA.y, bp1);  fma2(acc[6], aB.x, bp1);  fma2(acc[7], aB.y, bp1);
            fma2(acc[8], aA.x, bp2);  fma2(acc[9], aA.y, bp2);  fma2(acc[10], aB.x, bp2); fma2(acc[11], aB.y, bp2);
            fma2(acc[12], aA.x, bp3); fma2(acc[13], aA.y, bp3); fma2(acc[14], aB.x, bp3); fma2(acc[15], aB.y, bp3);
        }
        __syncthreads();
    }
    float o[8][4];
#pragma unroll
    for (int c = 0; c < 4; c++)
#pragma unroll
        for (int rp = 0; rp < 4; rp++) {
            float2 v = upk(acc[c * 4 + rp]);
            o[rp * 2][c] = v.x;
            o[rp * 2 + 1][c] = v.y;
        }
    int gc0 = colBase + tx * 4;
    if (gc0 < NC) {
        float bb[4];
#pragma unroll
        for (int c = 0; c < 4; c++) bb[c] = __ldg(&b2l[gc0 + c]);
#pragma unroll
        for (int r = 0; r < 8; r++) {
            int gr = rowBase + ty * 8 + r;
            if (gr < NNODES) {
                float4 v;
                v.x = o[r][0] + bb[0];
                v.y = o[r][1] + bb[1];
                v.z = o[r][2] + bb[2];
                v.w = o[r][3] + bb[3];
                *reinterpret_cast<float4*>(g_h + (size_t)gr * HDIM + gc0) = v;
            }
        }
    }
}

// ---------------- Pooling scatter: gsum[batch[n]] += h[n]; gcnt[batch[n]] += 1 ----------------
__global__ void pool_kernel(const int* __restrict__ batch) {
    int n = blockIdx.x * 8 + (threadIdx.x >> 5);
    if (n >= NNODES) return;
    int lane = threadIdx.x & 31;
    int g = __ldg(&batch[n]);
    const float4* hr = reinterpret_cast<const float4*>(g_h + (size_t)n * HDIM);
    float* gs = g_gsum + (size_t)g * HDIM;
#pragma unroll 3
    for (int c = lane; c < HDIM / 4; c += 32)
        red_add_v4(gs + 4 * c, hr[c]);
    if (lane == 0) atomicAdd(&g_gcnt[g], 1.0f);
}

// ---------------- Final: graph_feature + logits ----------------
__global__ void final_kernel(const float* __restrict__ cls_W, const float* __restrict__ cls_b,
                             float* __restrict__ out, int write_gf) {
    int g = blockIdx.x;
    int tid = threadIdx.x;
    float inv = 1.0f / fmaxf(g_gcnt[g], 1.0f);
    float d0 = 0.f, d1 = 0.f;
    for (int j = tid; j < HDIM; j += blockDim.x) {
        float gf = g_gsum[(size_t)g * HDIM + j] * inv;
        if (write_gf) out[2 * NGRAPHS + (size_t)g * HDIM + j] = gf;
        d0 += gf * __ldg(&cls_W[j * 2 + 0]);
        d1 += gf * __ldg(&cls_W[j * 2 + 1]);
    }
    __shared__ float s0[128], s1[128];
    s0[tid] = d0;
    s1[tid] = d1;
    __syncthreads();
    for (int o = 64; o > 0; o >>= 1) {
        if (tid < o) { s0[tid] += s0[tid + o]; s1[tid] += s1[tid + o]; }
        __syncthreads();
    }
    if (tid == 0) {
        out[g * 2 + 0] = s0[0] + __ldg(&cls_b[0]);
        out[g * 2 + 1] = s1[0] + __ldg(&cls_b[1]);
    }
}

// ---------------- Launcher ----------------
extern "C" void kernel_launch(void* const* d_in, const int* in_sizes, int n_in,
                              void* d_out, int out_size) {
    const int* x          = (const int*)d_in[0];
    const int* edge_index = (const int*)d_in[1];
    const int* edge_attr  = (const int*)d_in[2];
    const int* batch      = (const int*)d_in[3];
    const float* atom_emb = (const float*)d_in[4];
    const float* bond_emb = (const float*)d_in[5];
    const float* eps      = (const float*)d_in[6];
    const float* W1       = (const float*)d_in[7];
    const float* b1       = (const float*)d_in[8];
    const float* bn_gamma = (const float*)d_in[9];
    const float* bn_beta  = (const float*)d_in[10];
    const float* bn_mean  = (const float*)d_in[11];
    const float* bn_var   = (const float*)d_in[12];
    const float* W2       = (const float*)d_in[13];
    const float* b2       = (const float*)d_in[14];
    const float* cls_W    = (const float*)d_in[15];
    const float* cls_b    = (const float*)d_in[16];
    float* out = (float*)d_out;

    // Atom encoder
    atom_kernel<<<NNODES, 128>>>(x, atom_emb);
    // Zero pooling accumulators (pooling happens at the end)
    zero_pool_kernel<<<1184, 256>>>();

    dim3 g1grid((H2DIM + BN - 1) / BN, (NNODES + BM - 1) / BM); // 10 x 1563
    dim3 g2grid((HDIM + BN - 1) / BN, (NNODES + BM - 1) / BM);  // 5 x 1563

    for (int l = 0; l < NLAYERS; l++) {
        zero_agg_kernel<<<4096, 256>>>();
        edge_kernel<<<(NEDGES + 7) / 8, 256>>>(edge_index, edge_attr,
                                               bond_emb + (size_t)l * 3 * 16 * HDIM);
        gemm1_kernel<<<g1grid, 256>>>(W1 + (size_t)l * HDIM * H2DIM,
                                      b1 + (size_t)l * H2DIM,
                                      bn_gamma + (size_t)l * H2DIM,
                                      bn_beta + (size_t)l * H2DIM,
                                      bn_mean + (size_t)l * H2DIM,
                                      bn_var + (size_t)l * H2DIM,
                                      eps + l);
        gemm2_kernel<<<g2grid, 256>>>(W2 + (size_t)l * H2DIM * HDIM,
                                      b2 + (size_t)l * HDIM);
    }

    pool_kernel<<<(NNODES + 7) / 8, 256>>>(batch);
    int write_gf = (out_size >= 2 * NGRAPHS + NGRAPHS * HDIM) ? 1 : 0;
    final_kernel<<<NGRAPHS, 128>>>(cls_W, cls_b, out, write_gf);
}

// round 4
// speedup vs baseline: 1.3747x; 1.3747x over previous
#include <cuda_runtime.h>
#include <cstdint>
#include <cstddef>

// ---------------- Problem constants ----------------
#define NNODES 200000
#define NEDGES 400000
#define NGRAPHS 4096
#define HDIM 300
#define H2DIM 600
#define NLAYERS 5

// ---------------- Scratch (device globals; no allocation allowed) ----------------
__device__ float g_h[(size_t)NNODES * HDIM];     // node features
__device__ float g_agg[(size_t)NNODES * HDIM];   // scatter-add accumulator
__device__ float g_t[(size_t)NNODES * H2DIM];    // hidden 2H activations
__device__ float g_gsum[(size_t)NGRAPHS * HDIM]; // pooled sums
__device__ float g_gcnt[NGRAPHS];                // pooled counts

// ---------------- PTX helpers ----------------
__device__ __forceinline__ void red_add_v4(float* p, float4 v) {
    asm volatile("red.global.add.v4.f32 [%0], {%1, %2, %3, %4};"
                 :: "l"(p), "f"(v.x), "f"(v.y), "f"(v.z), "f"(v.w) : "memory");
}

// tf32 tensor-core mma: D(16x8) += A(16x8) * B(8x8), fp32 accum.
__device__ __forceinline__ void mma_tf32(float* d, const unsigned* a, const unsigned* b) {
    asm volatile(
        "mma.sync.aligned.m16n8k8.row.col.f32.tf32.tf32.f32 "
        "{%0,%1,%2,%3}, {%4,%5,%6,%7}, {%8,%9}, {%0,%1,%2,%3};"
        : "+f"(d[0]), "+f"(d[1]), "+f"(d[2]), "+f"(d[3])
        : "r"(a[0]), "r"(a[1]), "r"(a[2]), "r"(a[3]), "r"(b[0]), "r"(b[1]));
}

// Split v into hi (exactly tf32-representable: low 13 mantissa bits cleared)
// and lo = v - hi (exact in fp32).
__device__ __forceinline__ void tf32_split(float v, unsigned& hi, unsigned& lo) {
    unsigned hu = __float_as_uint(v) & 0xFFFFE000u;
    hi = hu;
    lo = __float_as_uint(v - __uint_as_float(hu));
}

// ---------------- Zeroing kernels ----------------
__global__ void zero_agg_kernel() {
    float4* p = reinterpret_cast<float4*>(g_agg);
    int n4 = (NNODES * HDIM) / 4;
    for (int i = blockIdx.x * blockDim.x + threadIdx.x; i < n4; i += gridDim.x * blockDim.x)
        p[i] = make_float4(0.f, 0.f, 0.f, 0.f);
}
__global__ void zero_pool_kernel() {
    float4* p = reinterpret_cast<float4*>(g_gsum);
    int n4 = (NGRAPHS * HDIM) / 4;
    for (int i = blockIdx.x * blockDim.x + threadIdx.x; i < n4; i += gridDim.x * blockDim.x)
        p[i] = make_float4(0.f, 0.f, 0.f, 0.f);
    for (int i = blockIdx.x * blockDim.x + threadIdx.x; i < NGRAPHS; i += gridDim.x * blockDim.x)
        g_gcnt[i] = 0.f;
}

// ---------------- Atom encoder ----------------
__global__ void atom_kernel(const int* __restrict__ x, const float* __restrict__ atom_emb) {
    int n = blockIdx.x;
    __shared__ int sx[9];
    if (threadIdx.x < 9) sx[threadIdx.x] = x[n * 9 + threadIdx.x];
    __syncthreads();
    for (int j = threadIdx.x; j < HDIM; j += blockDim.x) {
        float s = 0.f;
#pragma unroll
        for (int f = 0; f < 9; f++)
            s += __ldg(&atom_emb[((size_t)(f * 120 + sx[f])) * HDIM + j]);
        g_h[(size_t)n * HDIM + j] = s;
    }
}

// ---------------- Edge kernel: agg[dst] += relu(h[src] + e) ----------------
__global__ void edge_kernel(const int* __restrict__ edge_index,
                            const int* __restrict__ edge_attr,
                            const float* __restrict__ bond_l) {
    int e = blockIdx.x * 8 + (threadIdx.x >> 5);
    if (e >= NEDGES) return;
    int lane = threadIdx.x & 31;
    int src = __ldg(&edge_index[e]);
    int dst = __ldg(&edge_index[NEDGES + e]);
    int a0 = __ldg(&edge_attr[e * 3 + 0]);
    int a1 = __ldg(&edge_attr[e * 3 + 1]);
    int a2 = __ldg(&edge_attr[e * 3 + 2]);
    const float4* b0 = reinterpret_cast<const float4*>(bond_l + (size_t)(0 * 16 + a0) * HDIM);
    const float4* b1 = reinterpret_cast<const float4*>(bond_l + (size_t)(1 * 16 + a1) * HDIM);
    const float4* b2 = reinterpret_cast<const float4*>(bond_l + (size_t)(2 * 16 + a2) * HDIM);
    const float4* hs = reinterpret_cast<const float4*>(g_h + (size_t)src * HDIM);
    float* ag = g_agg + (size_t)dst * HDIM;
#pragma unroll 3
    for (int c = lane; c < HDIM / 4; c += 32) {
        float4 e0 = __ldg(&b0[c]);
        float4 e1 = __ldg(&b1[c]);
        float4 e2 = __ldg(&b2[c]);
        float4 hv = hs[c];
        float4 m;
        m.x = fmaxf(hv.x + e0.x + e1.x + e2.x, 0.f);
        m.y = fmaxf(hv.y + e0.y + e1.y + e2.y, 0.f);
        m.z = fmaxf(hv.z + e0.z + e1.z + e2.z, 0.f);
        m.w = fmaxf(hv.w + e0.w + e1.w + e2.w, 0.f);
        red_add_v4(ag + 4 * c, m);
    }
}

// ---------------- Tensor-core GEMM (3xTF32 mma.sync) ----------------
// Block tile 128x128, 8 warps, each warp 64x32 (4x4 m16n8k8 tiles per k8).
// Each operand split hi/lo; acc += ah*bh + al*bh + ah*bl  (lo*lo dropped).
// MODE 1: A = (1+eps)*g_h + g_agg [K=300], B = W1 [300,600], epilogue BN+ReLU -> g_t
// MODE 2: A = g_t [K=600],           B = W2 [600,300], epilogue +b2      -> g_h
#define GBM 128
#define GBN 128
#define GKC 16
#define SA_STRIDE 20
#define SB_STRIDE 132

template <int MODE>
__global__ __launch_bounds__(256) void gemm_mma_kernel(
    const float* __restrict__ Bmat,
    const float* __restrict__ bias,
    const float* __restrict__ gml, const float* __restrict__ btl,
    const float* __restrict__ mnl, const float* __restrict__ vrl,
    const float* __restrict__ epsp) {
    constexpr int K = (MODE == 1) ? HDIM : H2DIM;
    constexpr int NC = (MODE == 1) ? H2DIM : HDIM;
    constexpr int NKT = (K + GKC - 1) / GKC;

    __shared__ float As[GBM][SA_STRIDE];
    __shared__ float Bs[GKC][SB_STRIDE];

    int tid = threadIdx.x;
    int w = tid >> 5, lane = tid & 31;
    int wm = w & 1, wn = w >> 1;
    int gid = lane >> 2, tig = lane & 3;
    int rowBase = blockIdx.y * GBM, colBase = blockIdx.x * GBN;

    float epv = 0.f;
    if (MODE == 1) epv = 1.0f + __ldg(epsp);

    float acc[4][4][4];
#pragma unroll
    for (int mt = 0; mt < 4; mt++)
#pragma unroll
        for (int nt = 0; nt < 4; nt++)
#pragma unroll
            for (int i = 0; i < 4; i++) acc[mt][nt][i] = 0.f;

    auto loadA = [&](int kt, float4* r) {
#pragma unroll
        for (int i = 0; i < 2; i++) {
            int id = tid * 2 + i;
            int row = id >> 2, q = id & 3;
            int gr = rowBase + row;
            int gk = kt * GKC + q * 4;
            float4 v = make_float4(0.f, 0.f, 0.f, 0.f);
            if (gk < K && gr < NNODES) {
                if (MODE == 1) {
                    float4 hv = *reinterpret_cast<const float4*>(g_h + (size_t)gr * HDIM + gk);
                    float4 gv = *reinterpret_cast<const float4*>(g_agg + (size_t)gr * HDIM + gk);
                    v.x = fmaf(epv, hv.x, gv.x);
                    v.y = fmaf(epv, hv.y, gv.y);
                    v.z = fmaf(epv, hv.z, gv.z);
                    v.w = fmaf(epv, hv.w, gv.w);
                } else {
                    v = *reinterpret_cast<const float4*>(g_t + (size_t)gr * H2DIM + gk);
                }
            }
            r[i] = v;
        }
    };
    auto loadB = [&](int kt, float4* r) {
#pragma unroll
        for (int i = 0; i < 2; i++) {
            int id = tid * 2 + i;
            int k = id >> 5, n4 = id & 31;
            int gk = kt * GKC + k;
            int gc = colBase + n4 * 4;
            float4 v = make_float4(0.f, 0.f, 0.f, 0.f);
            if (gk < K && gc < NC)
                v = *reinterpret_cast<const float4*>(Bmat + (size_t)gk * NC + gc);
            r[i] = v;
        }
    };

    float4 aCur[2], bCur[2], aNxt[2], bNxt[2];
    loadA(0, aCur);
    loadB(0, bCur);

    for (int kt = 0; kt < NKT; kt++) {
        __syncthreads();
#pragma unroll
        for (int i = 0; i < 2; i++) {
            int id = tid * 2 + i;
            int row = id >> 2, q = id & 3;
            *reinterpret_cast<float4*>(&As[row][q * 4]) = aCur[i];
            int k = id >> 5, n4 = id & 31;
            *reinterpret_cast<float4*>(&Bs[k][n4 * 4]) = bCur[i];
        }
        __syncthreads();

        bool more = (kt + 1 < NKT);
        if (more) {
            loadA(kt + 1, aNxt);
            loadB(kt + 1, bNxt);
        }

#pragma unroll
        for (int kh = 0; kh < 2; kh++) {
            int kb = kh * 8;
            unsigned afh[4][4], afl[4][4];
#pragma unroll
            for (int mt = 0; mt < 4; mt++) {
                int r0 = wm * 64 + mt * 16 + gid;
                tf32_split(As[r0][kb + tig],         afh[mt][0], afl[mt][0]);
                tf32_split(As[r0 + 8][kb + tig],     afh[mt][1], afl[mt][1]);
                tf32_split(As[r0][kb + tig + 4],     afh[mt][2], afl[mt][2]);
                tf32_split(As[r0 + 8][kb + tig + 4], afh[mt][3], afl[mt][3]);
            }
            unsigned bfh[4][2], bfl[4][2];
#pragma unroll
            for (int nt = 0; nt < 4; nt++) {
                int c = wn * 32 + nt * 8 + gid;
                tf32_split(Bs[kb + tig][c],     bfh[nt][0], bfl[nt][0]);
                tf32_split(Bs[kb + tig + 4][c], bfh[nt][1], bfl[nt][1]);
            }
#pragma unroll
            for (int mt = 0; mt < 4; mt++)
#pragma unroll
                for (int nt = 0; nt < 4; nt++) {
                    mma_tf32(acc[mt][nt], afh[mt], bfh[nt]);
                    mma_tf32(acc[mt][nt], afl[mt], bfh[nt]);
                    mma_tf32(acc[mt][nt], afh[mt], bfl[nt]);
                }
        }

        if (more) {
#pragma unroll
            for (int i = 0; i < 2; i++) { aCur[i] = aNxt[i]; bCur[i] = bNxt[i]; }
        }
    }

    // Epilogue
#pragma unroll
    for (int nt = 0; nt < 4; nt++) {
        int c = colBase + wn * 32 + nt * 8 + 2 * tig;
        if (c >= NC) continue;  // pairs (c, c+1) never straddle NC (NC even, c even)
        float s0, s1, t0, t1;
        if (MODE == 1) {
            s0 = __ldg(&gml[c]) * rsqrtf(__ldg(&vrl[c]) + 1e-5f);
            t0 = (__ldg(&bias[c]) - __ldg(&mnl[c])) * s0 + __ldg(&btl[c]);
            s1 = __ldg(&gml[c + 1]) * rsqrtf(__ldg(&vrl[c + 1]) + 1e-5f);
            t1 = (__ldg(&bias[c + 1]) - __ldg(&mnl[c + 1])) * s1 + __ldg(&btl[c + 1]);
        } else {
            s0 = s1 = 1.f;
            t0 = __ldg(&bias[c]);
            t1 = __ldg(&bias[c + 1]);
        }
#pragma unroll
        for (int mt = 0; mt < 4; mt++) {
            int r0 = rowBase + wm * 64 + mt * 16 + gid;
            int r1 = r0 + 8;
            if (r0 < NNODES) {
                float v0 = fmaf(acc[mt][nt][0], s0, t0);
                float v1 = fmaf(acc[mt][nt][1], s1, t1);
                float2 o;
                if (MODE == 1) {
                    o.x = fmaxf(v0, 0.f);
                    o.y = fmaxf(v1, 0.f);
                    *reinterpret_cast<float2*>(g_t + (size_t)r0 * H2DIM + c) = o;
                } else {
                    o.x = v0;
                    o.y = v1;
                    *reinterpret_cast<float2*>(g_h + (size_t)r0 * HDIM + c) = o;
                }
            }
            if (r1 < NNODES) {
                float v0 = fmaf(acc[mt][nt][2], s0, t0);
                float v1 = fmaf(acc[mt][nt][3], s1, t1);
                float2 o;
                if (MODE == 1) {
                    o.x = fmaxf(v0, 0.f);
                    o.y = fmaxf(v1, 0.f);
                    *reinterpret_cast<float2*>(g_t + (size_t)r1 * H2DIM + c) = o;
                } else {
                    o.x = v0;
                    o.y = v1;
                    *reinterpret_cast<float2*>(g_h + (size_t)r1 * HDIM + c) = o;
                }
            }
        }
    }
}

// ---------------- Pooling scatter ----------------
__global__ void pool_kernel(const int* __restrict__ batch) {
    int n = blockIdx.x * 8 + (threadIdx.x >> 5);
    if (n >= NNODES) return;
    int lane = threadIdx.x & 31;
    int g = __ldg(&batch[n]);
    const float4* hr = reinterpret_cast<const float4*>(g_h + (size_t)n * HDIM);
    float* gs = g_gsum + (size_t)g * HDIM;
#pragma unroll 3
    for (int c = lane; c < HDIM / 4; c += 32)
        red_add_v4(gs + 4 * c, hr[c]);
    if (lane == 0) atomicAdd(&g_gcnt[g], 1.0f);
}

// ---------------- Final: graph_feature + logits ----------------
__global__ void final_kernel(const float* __restrict__ cls_W, const float* __restrict__ cls_b,
                             float* __restrict__ out, int write_gf) {
    int g = blockIdx.x;
    int tid = threadIdx.x;
    float inv = 1.0f / fmaxf(g_gcnt[g], 1.0f);
    float d0 = 0.f, d1 = 0.f;
    for (int j = tid; j < HDIM; j += blockDim.x) {
        float gf = g_gsum[(size_t)g * HDIM + j] * inv;
        if (write_gf) out[2 * NGRAPHS + (size_t)g * HDIM + j] = gf;
        d0 += gf * __ldg(&cls_W[j * 2 + 0]);
        d1 += gf * __ldg(&cls_W[j * 2 + 1]);
    }
    __shared__ float s0[128], s1[128];
    s0[tid] = d0;
    s1[tid] = d1;
    __syncthreads();
    for (int o = 64; o > 0; o >>= 1) {
        if (tid < o) { s0[tid] += s0[tid + o]; s1[tid] += s1[tid + o]; }
        __syncthreads();
    }
    if (tid == 0) {
        out[g * 2 + 0] = s0[0] + __ldg(&cls_b[0]);
        out[g * 2 + 1] = s1[0] + __ldg(&cls_b[1]);
    }
}

// ---------------- Launcher ----------------
extern "C" void kernel_launch(void* const* d_in, const int* in_sizes, int n_in,
                              void* d_out, int out_size) {
    const int* x          = (const int*)d_in[0];
    const int* edge_index = (const int*)d_in[1];
    const int* edge_attr  = (const int*)d_in[2];
    const int* batch      = (const int*)d_in[3];
    const float* atom_emb = (const float*)d_in[4];
    const float* bond_emb = (const float*)d_in[5];
    const float* eps      = (const float*)d_in[6];
    const float* W1       = (const float*)d_in[7];
    const float* b1       = (const float*)d_in[8];
    const float* bn_gamma = (const float*)d_in[9];
    const float* bn_beta  = (const float*)d_in[10];
    const float* bn_mean  = (const float*)d_in[11];
    const float* bn_var   = (const float*)d_in[12];
    const float* W2       = (const float*)d_in[13];
    const float* b2       = (const float*)d_in[14];
    const float* cls_W    = (const float*)d_in[15];
    const float* cls_b    = (const float*)d_in[16];
    float* out = (float*)d_out;

    atom_kernel<<<NNODES, 128>>>(x, atom_emb);
    zero_pool_kernel<<<1184, 256>>>();

    dim3 g1grid((H2DIM + GBN - 1) / GBN, (NNODES + GBM - 1) / GBM); // 5 x 1563
    dim3 g2grid((HDIM + GBN - 1) / GBN, (NNODES + GBM - 1) / GBM);  // 3 x 1563

    for (int l = 0; l < NLAYERS; l++) {
        zero_agg_kernel<<<4096, 256>>>();
        edge_kernel<<<(NEDGES + 7) / 8, 256>>>(edge_index, edge_attr,
                                               bond_emb + (size_t)l * 3 * 16 * HDIM);
        gemm_mma_kernel<1><<<g1grid, 256>>>(W1 + (size_t)l * HDIM * H2DIM,
                                            b1 + (size_t)l * H2DIM,
                                            bn_gamma + (size_t)l * H2DIM,
                                            bn_beta + (size_t)l * H2DIM,
                                            bn_mean + (size_t)l * H2DIM,
                                            bn_var + (size_t)l * H2DIM,
                                            eps + l);
        gemm_mma_kernel<2><<<g2grid, 256>>>(W2 + (size_t)l * H2DIM * HDIM,
                                            b2 + (size_t)l * HDIM,
                                            nullptr, nullptr, nullptr, nullptr, nullptr);
    }

    pool_kernel<<<(NNODES + 7) / 8, 256>>>(batch);
    int write_gf = (out_size >= 2 * NGRAPHS + NGRAPHS * HDIM) ? 1 : 0;
    final_kernel<<<NGRAPHS, 128>>>(cls_W, cls_b, out, write_gf);
}